// round 5
// baseline (speedup 1.0000x reference)
#include <cuda_runtime.h>
#include <cuda_bf16.h>
#include <math.h>

typedef unsigned long long ull;

// Problem constants
#define BB   256          // batch
#define TT   512          // seq len
#define HH   256          // hidden
#define GG   1024         // 4*H gates
#define CC   128          // classes
#define MM   (BB*TT)      // 131072 rows for input GEMMs

// ---------------- scratch (device globals; no allocs allowed) ----------------
__device__ float g_GX[(size_t)MM * GG];      // 512 MB  pre-activation gates (per layer, reused)
__device__ float g_HBUF[(size_t)MM * HH];    // 128 MB  layer-0 hidden states (input to layer-1 GEMM)
__device__ float g_H0[BB * HH];
__device__ float g_H1[BB * HH];
__device__ unsigned int g_bar;               // grid barrier counter

// ---------------- packed f32x2 helpers (Blackwell FFMA2 path) ----------------
__device__ __forceinline__ ull pack2(float x, float y) {
    ull r;
    asm("mov.b64 %0, {%1, %2};" : "=l"(r) : "f"(x), "f"(y));
    return r;
}
__device__ __forceinline__ float2 unpack2(ull v) {
    float2 r;
    asm("mov.b64 {%0, %1}, %2;" : "=f"(r.x), "=f"(r.y) : "l"(v));
    return r;
}
__device__ __forceinline__ ull ffma2x(ull a, ull b, ull c) {
    ull d;
    asm("fma.rn.f32x2 %0, %1, %2, %3;" : "=l"(d) : "l"(a), "l"(b), "l"(c));
    return d;
}

// fast activations (error ~1e-6, well inside 1e-3 budget)
__device__ __forceinline__ float fsigm(float x) {
    float e = __expf(-x);
    return __fdividef(1.0f, 1.0f + e);
}
__device__ __forceinline__ float ftanh(float x) {
    float e = __expf(2.0f * x);           // overflow -> inf -> result 1 (correct)
    return 1.0f - __fdividef(2.0f, e + 1.0f);
}

// ---------------- big GEMM:  Cout[m,n] = sum_k A[m,k]*W[n,k] + b1[n] + b2[n] --
// A: [MM,256] row-major (x, or g_HBUF), W: [1024,256] row-major.
// Tiles: BM=128, BN=64, BK=16, 256 threads, thread tile 8x4 (4 m-pairs x 4 n).
__global__ void __launch_bounds__(256) gemm_gx(const float* __restrict__ Aext,
                                               int useExt,
                                               const float* __restrict__ W,
                                               const float* __restrict__ b1,
                                               const float* __restrict__ b2) {
    __shared__ __align__(16) float As[16][128];
    __shared__ __align__(16) float Bs[16][64];

    const float* __restrict__ A = useExt ? Aext : g_HBUF;
    float* __restrict__ Cout = g_GX;

    const int tid = threadIdx.x;
    const int ty = tid >> 4;          // 0..15  (m group of 8)
    const int tx = tid & 15;          // 0..15  (n group of 4)
    const int bm0 = blockIdx.y * 128;
    const int bn0 = blockIdx.x * 64;

    ull acc[4][4];
    #pragma unroll
    for (int i = 0; i < 4; i++)
        #pragma unroll
        for (int j = 0; j < 4; j++) acc[i][j] = 0ull;

    for (int k0 = 0; k0 < 256; k0 += 16) {
        #pragma unroll
        for (int i = 0; i < 2; i++) {
            int s = tid + i * 256;          // 0..511
            int row = s >> 2;               // 0..127
            int kg = (s & 3) * 4;           // 0,4,8,12
            float4 v = *(const float4*)&A[(size_t)(bm0 + row) * 256 + k0 + kg];
            As[kg + 0][row] = v.x; As[kg + 1][row] = v.y;
            As[kg + 2][row] = v.z; As[kg + 3][row] = v.w;
        }
        {
            int row = tid >> 2;             // 0..63
            int kg = (tid & 3) * 4;
            float4 v = *(const float4*)&W[(size_t)(bn0 + row) * 256 + k0 + kg];
            Bs[kg + 0][row] = v.x; Bs[kg + 1][row] = v.y;
            Bs[kg + 2][row] = v.z; Bs[kg + 3][row] = v.w;
        }
        __syncthreads();
        #pragma unroll
        for (int k = 0; k < 16; k++) {
            const ull* ap = (const ull*)&As[k][ty * 8];
            ull a0 = ap[0], a1 = ap[1], a2 = ap[2], a3 = ap[3];
            float4 bv = *(const float4*)&Bs[k][tx * 4];
            ull bb0 = pack2(bv.x, bv.x);
            ull bb1 = pack2(bv.y, bv.y);
            ull bb2 = pack2(bv.z, bv.z);
            ull bb3 = pack2(bv.w, bv.w);
            acc[0][0] = ffma2x(a0, bb0, acc[0][0]);
            acc[1][0] = ffma2x(a1, bb0, acc[1][0]);
            acc[2][0] = ffma2x(a2, bb0, acc[2][0]);
            acc[3][0] = ffma2x(a3, bb0, acc[3][0]);
            acc[0][1] = ffma2x(a0, bb1, acc[0][1]);
            acc[1][1] = ffma2x(a1, bb1, acc[1][1]);
            acc[2][1] = ffma2x(a2, bb1, acc[2][1]);
            acc[3][1] = ffma2x(a3, bb1, acc[3][1]);
            acc[0][2] = ffma2x(a0, bb2, acc[0][2]);
            acc[1][2] = ffma2x(a1, bb2, acc[1][2]);
            acc[2][2] = ffma2x(a2, bb2, acc[2][2]);
            acc[3][2] = ffma2x(a3, bb2, acc[3][2]);
            acc[0][3] = ffma2x(a0, bb3, acc[0][3]);
            acc[1][3] = ffma2x(a1, bb3, acc[1][3]);
            acc[2][3] = ffma2x(a2, bb3, acc[2][3]);
            acc[3][3] = ffma2x(a3, bb3, acc[3][3]);
        }
        __syncthreads();
    }

    float4 b1v = *(const float4*)&b1[bn0 + tx * 4];
    float4 b2v = *(const float4*)&b2[bn0 + tx * 4];
    float4 bias = make_float4(b1v.x + b2v.x, b1v.y + b2v.y,
                              b1v.z + b2v.z, b1v.w + b2v.w);
    #pragma unroll
    for (int i = 0; i < 4; i++) {
        float2 q0 = unpack2(acc[i][0]);
        float2 q1 = unpack2(acc[i][1]);
        float2 q2 = unpack2(acc[i][2]);
        float2 q3 = unpack2(acc[i][3]);
        size_t r0 = (size_t)(bm0 + ty * 8 + 2 * i);
        float4 v0 = make_float4(q0.x + bias.x, q1.x + bias.y, q2.x + bias.z, q3.x + bias.w);
        float4 v1 = make_float4(q0.y + bias.x, q1.y + bias.y, q2.y + bias.z, q3.y + bias.w);
        *(float4*)&Cout[r0 * GG + bn0 + tx * 4] = v0;
        *(float4*)&Cout[(r0 + 1) * GG + bn0 + tx * 4] = v1;
    }
}

// ---------------- barrier reset ----------------
__global__ void reset_bar() { g_bar = 0u; }

// ---------------- persistent recurrence kernel -------------------------------
// 128 blocks x 128 threads, all co-resident (<=148 SMs). Block owns
// 32 batch rows x 16 h-cols (x 4 gates). whh slice (64 rows x 256) in SMEM
// for the whole sequence; c state in registers; h double-buffered in global;
// software grid barrier between timesteps.
__global__ void __launch_bounds__(128, 1) lstm_persist(const float* __restrict__ whh,
                                                       int writeHbuf) {
    extern __shared__ float sm[];
    float* sWs = sm;              // [256][64]   weights, transposed [k][bh*4+g]
    float* sAs = sm + 256 * 64;   // [256][32]   h tile, transposed [k][row]

    const int tid  = threadIdx.x;
    const int bid  = blockIdx.x;
    const int hcol = tid & 15;
    const int rq   = tid >> 4;               // 0..7
    const int c0   = (bid & 15) * 16;        // h-col group
    const int bm   = (bid >> 4) * 32;        // batch-row group
    const int col  = c0 + hcol;

    // one-time weight stage: 64 gate-rows (bh*4+g) x 256 k
    for (int i = tid; i < 64 * 64; i += 128) {
        int lr = i >> 6;              // 0..63 local row
        int kk = (i & 63) * 4;        // k0
        int bh = lr >> 2, g = lr & 3;
        float4 v = *(const float4*)&whh[(size_t)(g * HH + c0 + bh) * HH + kk];
        sWs[(kk + 0) * 64 + lr] = v.x;
        sWs[(kk + 1) * 64 + lr] = v.y;
        sWs[(kk + 2) * 64 + lr] = v.z;
        sWs[(kk + 3) * 64 + lr] = v.w;
    }
    __syncthreads();

    float creg[4] = {0.f, 0.f, 0.f, 0.f};
    int rows[4];
    #pragma unroll
    for (int r = 0; r < 4; r++) rows[r] = bm + rq * 4 + r;

    for (int t = 0; t < TT; t++) {
        const float* __restrict__ hin  = (t & 1) ? g_H1 : g_H0;
        float* __restrict__       hout = (t & 1) ? g_H0 : g_H1;

        // prefetch GX preactivations (DRAM) early to hide latency behind k-loop
        float pg_i[4], pg_f[4], pg_g[4], pg_o[4];
        #pragma unroll
        for (int r = 0; r < 4; r++) {
            size_t base = ((size_t)rows[r] * TT + t) * GG + col;
            pg_i[r] = g_GX[base];
            pg_f[r] = g_GX[base + 256];
            pg_g[r] = g_GX[base + 512];
            pg_o[r] = g_GX[base + 768];
        }

        ull ai0 = 0, ai1 = 0, af0 = 0, af1 = 0;
        ull ag0 = 0, ag1 = 0, ao0 = 0, ao1 = 0;

        if (t > 0) {   // h == 0 at t=0, recurrent term vanishes
            // stage hin tile (32 rows x 256 k), transposed
            int r  = tid & 31;
            int kc = tid >> 5;                         // 0..3, 64 k each
            const float* hrow = &hin[(bm + r) * HH + kc * 64];
            #pragma unroll
            for (int j = 0; j < 16; j++) {
                float4 v = *(const float4*)&hrow[j * 4];
                int k0 = kc * 64 + j * 4;
                sAs[(k0 + 0) * 32 + r] = v.x;
                sAs[(k0 + 1) * 32 + r] = v.y;
                sAs[(k0 + 2) * 32 + r] = v.z;
                sAs[(k0 + 3) * 32 + r] = v.w;
            }
            __syncthreads();

            const float* ap = &sAs[rq * 4];
            const float* bp = &sWs[hcol * 4];
            #pragma unroll 8
            for (int k = 0; k < 256; k++) {
                ull a0 = *(const ull*)(ap + k * 32);
                ull a1 = *(const ull*)(ap + k * 32 + 2);
                float4 bv = *(const float4*)(bp + k * 64);   // (i,f,g,o)
                ull bi = pack2(bv.x, bv.x);
                ull bf = pack2(bv.y, bv.y);
                ull bg = pack2(bv.z, bv.z);
                ull bo = pack2(bv.w, bv.w);
                ai0 = ffma2x(a0, bi, ai0); ai1 = ffma2x(a1, bi, ai1);
                af0 = ffma2x(a0, bf, af0); af1 = ffma2x(a1, bf, af1);
                ag0 = ffma2x(a0, bg, ag0); ag1 = ffma2x(a1, bg, ag1);
                ao0 = ffma2x(a0, bo, ao0); ao1 = ffma2x(a1, bo, ao1);
            }
        }

        float iv[4], fv[4], gv[4], ov[4];
        {
            float2 p;
            p = unpack2(ai0); iv[0] = p.x; iv[1] = p.y;
            p = unpack2(ai1); iv[2] = p.x; iv[3] = p.y;
            p = unpack2(af0); fv[0] = p.x; fv[1] = p.y;
            p = unpack2(af1); fv[2] = p.x; fv[3] = p.y;
            p = unpack2(ag0); gv[0] = p.x; gv[1] = p.y;
            p = unpack2(ag1); gv[2] = p.x; gv[3] = p.y;
            p = unpack2(ao0); ov[0] = p.x; ov[1] = p.y;
            p = unpack2(ao1); ov[2] = p.x; ov[3] = p.y;
        }

        #pragma unroll
        for (int r = 0; r < 4; r++) {
            float si = fsigm(iv[r] + pg_i[r]);
            float sf = fsigm(fv[r] + pg_f[r]);
            float tg = ftanh(gv[r] + pg_g[r]);
            float so = fsigm(ov[r] + pg_o[r]);
            float c  = sf * creg[r] + si * tg;
            creg[r]  = c;
            float h  = so * ftanh(c);
            hout[rows[r] * HH + col] = h;
            if (writeHbuf)
                g_HBUF[((size_t)rows[r] * TT + t) * HH + col] = h;
        }

        // software grid barrier (not needed after the final step)
        if (t < TT - 1) {
            __syncthreads();
            if (tid == 0) {
                __threadfence();                       // release h writes
                atomicAdd(&g_bar, 1u);
                unsigned target = (unsigned)(t + 1) * 128u;
                unsigned v;
                do {
                    asm volatile("ld.global.acquire.gpu.u32 %0, [%1];"
                                 : "=r"(v) : "l"(&g_bar));
                } while (v < target);
            }
            __syncthreads();
        }
    }
}

// ---------------- FC + log_softmax ------------------------------------------
__global__ void __launch_bounds__(128) fc_kernel(const float* __restrict__ wfc,
                                                 const float* __restrict__ bfc,
                                                 float* __restrict__ out) {
    const int b = blockIdx.x;
    const int tid = threadIdx.x;  // 128 = one class per thread
    __shared__ float h[256];
    h[tid] = g_H0[b * HH + tid];
    h[tid + 128] = g_H0[b * HH + tid + 128];
    __syncthreads();

    float acc = bfc[tid];
    const float* w = wfc + (size_t)tid * HH;
    #pragma unroll 8
    for (int k = 0; k < 256; k++) acc += h[k] * w[k];

    float m = acc;
    #pragma unroll
    for (int o = 16; o > 0; o >>= 1)
        m = fmaxf(m, __shfl_xor_sync(0xffffffffu, m, o));
    __shared__ float sm[4], ss[4];
    int wid = tid >> 5, lane = tid & 31;
    if (lane == 0) sm[wid] = m;
    __syncthreads();
    m = fmaxf(fmaxf(sm[0], sm[1]), fmaxf(sm[2], sm[3]));

    float e = expf(acc - m);
    float s = e;
    #pragma unroll
    for (int o = 16; o > 0; o >>= 1)
        s += __shfl_xor_sync(0xffffffffu, s, o);
    if (lane == 0) ss[wid] = s;
    __syncthreads();
    s = ss[0] + ss[1] + ss[2] + ss[3];

    out[b * CC + tid] = acc - m - logf(s);
}

// ---------------- launch ------------------------------------------------------
extern "C" void kernel_launch(void* const* d_in, const int* in_sizes, int n_in,
                              void* d_out, int out_size) {
    const float* x    = (const float*)d_in[0];
    const float* wih0 = (const float*)d_in[1];
    const float* whh0 = (const float*)d_in[2];
    const float* bih0 = (const float*)d_in[3];
    const float* bhh0 = (const float*)d_in[4];
    const float* wih1 = (const float*)d_in[5];
    const float* whh1 = (const float*)d_in[6];
    const float* bih1 = (const float*)d_in[7];
    const float* bhh1 = (const float*)d_in[8];
    const float* wfc  = (const float*)d_in[9];
    const float* bfc  = (const float*)d_in[10];
    float* out = (float*)d_out;

    const int persist_smem = (256 * 64 + 256 * 32) * (int)sizeof(float); // 96 KB
    static bool attr_set = false;
    if (!attr_set) {
        cudaFuncSetAttribute(lstm_persist,
                             cudaFuncAttributeMaxDynamicSharedMemorySize,
                             persist_smem);
        attr_set = true;
    }

    dim3 gemm_grid(16, 1024);   // N/64, M/128

    // Layer 0
    gemm_gx<<<gemm_grid, 256>>>(x, 1, wih0, bih0, bhh0);
    reset_bar<<<1, 1>>>();
    lstm_persist<<<128, 128, persist_smem>>>(whh0, 1);

    // Layer 1
    gemm_gx<<<gemm_grid, 256>>>(nullptr, 0, wih1, bih1, bhh1);
    reset_bar<<<1, 1>>>();
    lstm_persist<<<128, 128, persist_smem>>>(whh1, 0);

    // Head
    fc_kernel<<<256, 128>>>(wfc, bfc, out);
}